// round 17
// baseline (speedup 1.0000x reference)
#include <cuda_runtime.h>
#include <cuda_fp16.h>
#include <cstdint>

#define D_DIM   256
#define BM      64            // tokens per block-iteration
#define BN      64            // codes per tile (2 warps x n32)
#define THREADS 256

#define ZROWB   528           // z rows padded: odd 16B stride -> ldsm conflict-free
#define ZSPLIT  (64 * ZROWB)  // 33792 B per z split (h, l)
#define OFF_B   (2 * ZSPLIT)  // 67584
#define BROW    512           // B rows unpadded (bulk-copy contiguous); XOR swizzle
#define BSPLIT  (64 * BROW)   // 32768 B per B split per buffer
#define BBUF    (2 * BSPLIT)  // 65536 B per B buffer (h + l)
#define SMEM_SZ (OFF_B + 2 * BBUF)   // 198656 B

__device__ float  g_csq[4096];
__device__ __half g_cbH[4096 * 256];   // pre-swizzled: chunk c at (c&24)|((c&7)^(k&7))
__device__ __half g_cbL[4096 * 256];

// ---------------- helpers -------------------------------------------------
__device__ __forceinline__ uint32_t smem_u32(const void* p) {
    uint32_t a;
    asm("{ .reg .u64 t; cvta.to.shared.u64 t, %1; cvt.u32.u64 %0, t; }"
        : "=r"(a) : "l"(p));
    return a;
}
__device__ __forceinline__ void split2(float v, __half& h, __half& l) {
    h = __float2half_rn(v);
    l = __float2half_rn(v - __half2float(h));   // v-h exact in fp32
}
__device__ __forceinline__ uint32_t packh(__half lo, __half hi) {
    return ((uint32_t)__half_as_ushort(hi) << 16) | __half_as_ushort(lo);
}
__device__ __forceinline__ void ldsm4(uint32_t* r, uint32_t a) {
    asm volatile("ldmatrix.sync.aligned.m8n8.x4.shared.b16 {%0,%1,%2,%3}, [%4];"
                 : "=r"(r[0]), "=r"(r[1]), "=r"(r[2]), "=r"(r[3]) : "r"(a));
}
__device__ __forceinline__ void mma16816(float* c, const uint32_t* a,
                                         uint32_t b0, uint32_t b1) {
    asm volatile(
        "mma.sync.aligned.m16n8k16.row.col.f32.f16.f16.f32 "
        "{%0,%1,%2,%3}, {%4,%5,%6,%7}, {%8,%9}, {%0,%1,%2,%3};"
        : "+f"(c[0]), "+f"(c[1]), "+f"(c[2]), "+f"(c[3])
        : "r"(a[0]), "r"(a[1]), "r"(a[2]), "r"(a[3]), "r"(b0), "r"(b1));
}
__device__ __forceinline__ void bulk_g2s(uint32_t dst, const void* src,
                                         uint32_t bytes, uint32_t mbar) {
    asm volatile(
        "cp.async.bulk.shared::cluster.global.mbarrier::complete_tx::bytes "
        "[%0], [%1], %2, [%3];"
        :: "r"(dst), "l"(src), "r"(bytes), "r"(mbar) : "memory");
}
__device__ __forceinline__ void mbar_init(uint32_t mbar, uint32_t cnt) {
    asm volatile("mbarrier.init.shared.b64 [%0], %1;" :: "r"(mbar), "r"(cnt) : "memory");
}
__device__ __forceinline__ void mbar_expect_tx(uint32_t mbar, uint32_t bytes) {
    asm volatile("mbarrier.arrive.expect_tx.shared.b64 _, [%0], %1;"
                 :: "r"(mbar), "r"(bytes) : "memory");
}
__device__ __forceinline__ void mbar_wait(uint32_t mbar, uint32_t parity) {
    asm volatile(
        "{\n\t.reg .pred P;\n"
        "W%=:\n\t"
        "mbarrier.try_wait.parity.acquire.cta.shared::cta.b64 P, [%0], %1, 0x989680;\n\t"
        "@!P bra W%=;\n\t}"
        :: "r"(mbar), "r"(parity) : "memory");
}

// ---------------- prologue kernels ----------------------------------------
__global__ void prep_cb_kernel(const float* __restrict__ cb, int nchunk) {
    int i = blockIdx.x * blockDim.x + threadIdx.x;
    if (i >= nchunk) return;
    int k = i >> 5, c = i & 31;                 // row k, logical 16B chunk c
    const float4* s = (const float4*)(cb + (size_t)k * D_DIM + c * 8);
    float4 f0 = __ldg(s), f1 = __ldg(s + 1);
    __half h[8], l[8];
    split2(f0.x, h[0], l[0]); split2(f0.y, h[1], l[1]);
    split2(f0.z, h[2], l[2]); split2(f0.w, h[3], l[3]);
    split2(f1.x, h[4], l[4]); split2(f1.y, h[5], l[5]);
    split2(f1.z, h[6], l[6]); split2(f1.w, h[7], l[7]);
    uint4 H, L;
    H.x = packh(h[0], h[1]); H.y = packh(h[2], h[3]);
    H.z = packh(h[4], h[5]); H.w = packh(h[6], h[7]);
    L.x = packh(l[0], l[1]); L.y = packh(l[2], l[3]);
    L.z = packh(l[4], l[5]); L.w = packh(l[6], l[7]);
    int p = (c & 24) | ((c & 7) ^ (k & 7));     // XOR swizzle baked into gmem
    ((uint4*)g_cbH)[(size_t)k * 32 + p] = H;
    ((uint4*)g_cbL)[(size_t)k * 32 + p] = L;
}
__global__ void csq_kernel(const float* __restrict__ cb, int K) {
    int k = blockIdx.x * (blockDim.x / 32) + (threadIdx.x >> 5);
    int lane = threadIdx.x & 31;
    if (k >= K) return;
    const float* row = cb + (size_t)k * D_DIM;
    float s = 0.f;
    #pragma unroll
    for (int d = lane; d < D_DIM; d += 32) {
        float v = row[d];
        s = fmaf(v, v, s);
    }
    #pragma unroll
    for (int o = 16; o; o >>= 1) s += __shfl_xor_sync(0xffffffffu, s, o);
    if (lane == 0) g_csq[k] = s;
}

// ---------------- main kernel (persistent) ---------------------------------
// 8 warps: wm = wid>>1 (token rows 16*wm..), wn = wid&1 (codes 32*wn..).
// fp16 2-split, 3 products (hh, hl, lh). A fragments live in REGISTERS for
// the whole block-iteration (z constant across tiles) -> B-only ldsm loop.
__global__ __launch_bounds__(THREADS, 1)
void vq_kernel(const float* __restrict__ z, const float* __restrict__ cb,
               float* __restrict__ zq, float* __restrict__ idx_out,
               int K, int write_idx, int nblk) {
    extern __shared__ char smem[];
    __shared__ uint64_t mbars[2];
    const uint32_t sbase = smem_u32(smem);
    const uint32_t mb0 = smem_u32(&mbars[0]);
    const uint32_t mb1 = smem_u32(&mbars[1]);

    const int tid  = threadIdx.x;
    const int lane = tid & 31;
    const int wid  = tid >> 5;
    const int wm   = wid >> 1;
    const int wn   = wid & 1;
    const int NT   = K / BN;               // 16

    if (tid == 0) { mbar_init(mb0, 1); mbar_init(mb1, 1); }

    const int lr = lane & 15, lh = lane >> 4;
    const int r7 = lr & 7;
    const uint32_t aAddr = sbase + (uint32_t)(wm * 16 + lr) * ZROWB + lh * 16;
    const uint32_t bRow0 = sbase + OFF_B + (uint32_t)(wn * 32 + lr) * BROW;

    bool first = true;

    for (int blk = blockIdx.x; blk < nblk; blk += gridDim.x) {
        const long m0 = (long)blk * BM;

        // ---- stage z splits into smem (row = tid>>2, 64 dims/thread) ----
        {
            int row = tid >> 2, seg = tid & 3;
            const float4* zr = (const float4*)(z + (m0 + row) * D_DIM) + seg * 16;
            char* zb = smem + row * ZROWB + seg * 128;
            #pragma unroll
            for (int q = 0; q < 16; q++) {
                float4 f = __ldg(zr + q);
                __half h0, l0, h1, l1, h2, l2, h3, l3;
                split2(f.x, h0, l0); split2(f.y, h1, l1);
                split2(f.z, h2, l2); split2(f.w, h3, l3);
                *(uint32_t*)(zb + 0 * ZSPLIT + q * 8)     = packh(h0, h1);
                *(uint32_t*)(zb + 0 * ZSPLIT + q * 8 + 4) = packh(h2, h3);
                *(uint32_t*)(zb + 1 * ZSPLIT + q * 8)     = packh(l0, l1);
                *(uint32_t*)(zb + 1 * ZSPLIT + q * 8 + 4) = packh(l2, l3);
            }
        }
        // first iteration: kick off B tiles 0 and 1 (later iters prefetch
        // them at the end of the previous block-iteration)
        if (first && tid == 0) {
            mbar_expect_tx(mb0, BBUF);
            bulk_g2s(sbase + OFF_B + 0 * BSPLIT, (const char*)g_cbH, BSPLIT, mb0);
            bulk_g2s(sbase + OFF_B + 1 * BSPLIT, (const char*)g_cbL, BSPLIT, mb0);
            mbar_expect_tx(mb1, BBUF);
            bulk_g2s(sbase + OFF_B + BBUF + 0 * BSPLIT, (const char*)g_cbH + BSPLIT, BSPLIT, mb1);
            bulk_g2s(sbase + OFF_B + BBUF + 1 * BSPLIT, (const char*)g_cbL + BSPLIT, BSPLIT, mb1);
        }
        first = false;
        __syncthreads();   // z smem + mbar init visible

        // ---- load ALL A fragments into registers (z constant over tiles) --
        uint32_t aH[16][4], aL[16][4];
        #pragma unroll
        for (int kk = 0; kk < 16; kk++) {
            ldsm4(aH[kk], aAddr + 0 * ZSPLIT + kk * 32);
            ldsm4(aL[kk], aAddr + 1 * ZSPLIT + kk * 32);
        }

        float bD[2] = {3.4e38f, 3.4e38f};
        int   bI[2] = {0, 0};

        for (int t = 0; t < NT; ++t) {
            mbar_wait((t & 1) ? mb1 : mb0, (t >> 1) & 1);

            const uint32_t bBase = bRow0 + (uint32_t)(t & 1) * BBUF;

            float acc[4][4];
            #pragma unroll
            for (int g = 0; g < 4; g++)
                #pragma unroll
                for (int r = 0; r < 4; r++) acc[g][r] = 0.f;

            #pragma unroll
            for (int kk = 0; kk < 16; ++kk) {
                const uint32_t hi16 = (uint32_t)(((2 * kk) & 24) << 4);
                const uint32_t sw16 = ((((uint32_t)((2 * kk) & 7) + lh) ^ r7) << 4);
                #pragma unroll
                for (int h = 0; h < 2; h++) {          // 16-code halves of n32
                    uint32_t bH[4], bL[4];
                    uint32_t ba = bBase + (uint32_t)(h * 16) * BROW + hi16 + sw16;
                    ldsm4(bH, ba + 0 * BSPLIT);
                    ldsm4(bL, ba + 1 * BSPLIT);
                    #pragma unroll
                    for (int s = 0; s < 2; s++) {      // n8 within 16 codes
                        float* a = acc[h * 2 + s];
                        mma16816(a, aH[kk], bH[s], bH[s + 2]);   // hh
                        mma16816(a, aH[kk], bL[s], bL[s + 2]);   // hl
                        mma16816(a, aL[kk], bH[s], bH[s + 2]);   // lh
                    }
                }
            }

            // per-tile argmin: dist = ||c||^2 - 2 z.c
            const int n0 = t * BN;
            #pragma unroll
            for (int g = 0; g < 4; g++) {
                int colb = n0 + wn * 32 + (g >> 1) * 16 + (g & 1) * 8 + 2 * (lane & 3);
                float q0 = g_csq[colb], q1 = g_csq[colb + 1];
                float d0 = fmaf(-2.f, acc[g][0], q0);
                float d1 = fmaf(-2.f, acc[g][1], q1);
                float d2 = fmaf(-2.f, acc[g][2], q0);
                float d3 = fmaf(-2.f, acc[g][3], q1);
                if (d0 < bD[0]) { bD[0] = d0; bI[0] = colb; }
                if (d1 < bD[0]) { bD[0] = d1; bI[0] = colb + 1; }
                if (d2 < bD[1]) { bD[1] = d2; bI[1] = colb; }
                if (d3 < bD[1]) { bD[1] = d3; bI[1] = colb + 1; }
            }

            __syncthreads();   // all warps done with buffer t&1

            if (t + 2 < NT && tid == 0) {
                uint32_t mb = (t & 1) ? mb1 : mb0;
                uint32_t dst = sbase + OFF_B + (uint32_t)(t & 1) * BBUF;
                size_t goff = (size_t)(t + 2) * BSPLIT;
                mbar_expect_tx(mb, BBUF);
                bulk_g2s(dst + 0 * BSPLIT, (const char*)g_cbH + goff, BSPLIT, mb);
                bulk_g2s(dst + 1 * BSPLIT, (const char*)g_cbL + goff, BSPLIT, mb);
            }
        }

        // ---- cross-thread argmin (8 slots per token row), alias z smem ----
        float* redD   = (float*)smem;            // [64][8]
        int*   redI   = (int*)(smem + 2048);     // [64][8]
        int*   rowIdx = (int*)(smem + 4096);     // [64]
        {
            int g = lane >> 2;
            int slot = wn * 4 + (lane & 3);
            int r0 = wm * 16 + g;
            redD[r0 * 8 + slot] = bD[0];        redI[r0 * 8 + slot] = bI[0];
            redD[(r0 + 8) * 8 + slot] = bD[1];  redI[(r0 + 8) * 8 + slot] = bI[1];
        }

        // prefetch next block-iteration's B tiles 0,1 (buffers now free)
        if (blk + gridDim.x < nblk && tid == 0) {
            mbar_expect_tx(mb0, BBUF);
            bulk_g2s(sbase + OFF_B + 0 * BSPLIT, (const char*)g_cbH, BSPLIT, mb0);
            bulk_g2s(sbase + OFF_B + 1 * BSPLIT, (const char*)g_cbL, BSPLIT, mb0);
            mbar_expect_tx(mb1, BBUF);
            bulk_g2s(sbase + OFF_B + BBUF + 0 * BSPLIT, (const char*)g_cbH + BSPLIT, BSPLIT, mb1);
            bulk_g2s(sbase + OFF_B + BBUF + 1 * BSPLIT, (const char*)g_cbL + BSPLIT, BSPLIT, mb1);
        }
        __syncthreads();
        if (tid < BM) {
            float bd = redD[tid * 8];
            int   bi = redI[tid * 8];
            #pragma unroll
            for (int s = 1; s < 8; s++) {
                float d = redD[tid * 8 + s];
                int  ii = redI[tid * 8 + s];
                if (d < bd || (d == bd && ii < bi)) { bd = d; bi = ii; }
            }
            rowIdx[tid] = bi;
            if (write_idx) idx_out[m0 + tid] = (float)bi;
        }
        __syncthreads();

        // ---- gather z_q = codebook[idx] from exact fp32 codebook ----
        float4* zqdst = (float4*)(zq + m0 * D_DIM);
        #pragma unroll 4
        for (int f = tid; f < BM * (D_DIM / 4); f += THREADS) {
            float4 v = __ldg((const float4*)(cb + (size_t)rowIdx[f >> 6] * D_DIM + (f & 63) * 4));
            zqdst[f] = v;
        }
        __syncthreads();   // rowIdx reads done before next iter overwrites smem
    }
}

// ---------------------------------------------------------------------------
extern "C" void kernel_launch(void* const* d_in, const int* in_sizes, int n_in,
                              void* d_out, int out_size) {
    const float* z  = (const float*)d_in[0];
    const float* cb = (const float*)d_in[1];
    const int zElems  = in_sizes[0];
    const int cbElems = in_sizes[1];
    const int ntok = zElems / D_DIM;
    const int K    = cbElems / D_DIM;
    const int nblk = ntok / BM;

    float* out     = (float*)d_out;
    float* idx_out = out + (size_t)zElems;
    const int write_idx = (out_size >= zElems + ntok) ? 1 : 0;

    csq_kernel<<<(K + 7) / 8, 256>>>(cb, K);
    prep_cb_kernel<<<(K * 32 + 255) / 256, 256>>>(cb, K * 32);

    cudaFuncSetAttribute(vq_kernel,
                         cudaFuncAttributeMaxDynamicSharedMemorySize, SMEM_SZ);
    const int grid = nblk < 148 ? nblk : 148;
    vq_kernel<<<grid, THREADS, SMEM_SZ>>>(z, cb, out, idx_out, K, write_idx, nblk);
}